// round 1
// baseline (speedup 1.0000x reference)
#include <cuda_runtime.h>

// FD_discretizer: structured 1024x1024 grid, extended 1026x1026.
// All reference index arrays are closed-form in (i,j); computed arithmetically.

#define NXg 1024
#define NYg 1024
#define EX  1026
#define EY  1026
#define NN  (NXg*NYg)
#define NEXTN (EX*EY)

#define T_NORMAL 0
#define T_INFLOW 4
#define T_OUTFLOW 5
#define T_WALL 6

#define PRESS_E (513*EX + 513)

// 15 SoA scratch arrays over the extended grid (static device globals: allowed).
__device__ float g_eu [NEXTN];
__device__ float g_ev [NEXTN];
__device__ float g_ep [NEXTN];
__device__ float g_eou[NEXTN];
__device__ float g_eov[NEXTN];
__device__ float g_U  [NEXTN];
__device__ float g_V  [NEXTN];
__device__ float g_Uo [NEXTN];
__device__ float g_Vo [NEXTN];
__device__ float g_a11[NEXTN];
__device__ float g_a22[NEXTN];
__device__ float g_pxx[NEXTN];
__device__ float g_pxy[NEXTN];
__device__ float g_pex[NEXTN];
__device__ float g_pey[NEXTN];

__device__ __forceinline__ int clampi(int x, int lo, int hi) {
    return x < lo ? lo : (x > hi ? hi : x);
}
// extended node (je,ie) -> original node index
__device__ __forceinline__ int eidx(int je, int ie) {
    return clampi(je - 1, 0, NYg - 1) * NXg + clampi(ie - 1, 0, NXg - 1);
}

struct F3 { float x, y, z; };

// node_type is closed-form: io==0 INFLOW, io==NX-1 OUTFLOW (overrides walls),
// jo edge WALL, else NORMAL.
__device__ __forceinline__ void dummy_uv(const float* __restrict__ uvp,
                                         const float* __restrict__ ny,
                                         int m, float& du, float& dv) {
    int io = m % NXg;
    int jo = m / NXg;
    bool bc = (io == 0) || (io != NXg - 1 && (jo == 0 || jo == NYg - 1));
    if (bc) { du = ny[3*m]; dv = ny[3*m+1]; }
    else    { du = uvp[3*m]; dv = uvp[3*m+1]; }
}
__device__ __forceinline__ float dummy_p(const float* __restrict__ uvp, int m) {
    int io = m % NXg;
    return (io == NXg - 1) ? 0.0f : uvp[3*m+2];
}

// BC-enforced extended value at (je,ie) for a uvp field.
__device__ __forceinline__ F3 ext_val(const float* __restrict__ uvp,
                                      const float* __restrict__ ny,
                                      int je, int ie) {
    F3 r;
    if (ie == 0 && je >= 1 && je <= EY - 2) {
        // left ghost: gt = INFLOW -> pmask
        int m1 = eidx(je, 1), m2 = eidx(je, 2);
        float du, dv; dummy_uv(uvp, ny, m1, du, dv);
        r.x = 2.0f*du - uvp[3*m2];
        r.y = 2.0f*dv - uvp[3*m2+1];
        r.z = uvp[3*m2+2];
    } else if (ie == EX - 1 && je >= 1 && je <= EY - 2) {
        // right ghost: gt = OUTFLOW -> uvmask
        int m1 = eidx(je, EX - 2), m2 = eidx(je, EX - 3);
        float dp = dummy_p(uvp, m1);
        r.x = uvp[3*m2];
        r.y = uvp[3*m2+1];
        r.z = 2.0f*dp - uvp[3*m2+2];
    } else if (je == 0 && ie >= 1 && ie <= EX - 2) {
        // bottom ghost: gt = WALL -> pmask
        int m1 = eidx(1, ie), m2 = eidx(2, ie);
        float du, dv; dummy_uv(uvp, ny, m1, du, dv);
        r.x = 2.0f*du - uvp[3*m2];
        r.y = 2.0f*dv - uvp[3*m2+1];
        r.z = uvp[3*m2+2];
    } else if (je == EY - 1 && ie >= 1 && ie <= EX - 2) {
        // top ghost: gt = WALL -> pmask
        int m1 = eidx(EY - 2, ie), m2 = eidx(EY - 3, ie);
        float du, dv; dummy_uv(uvp, ny, m1, du, dv);
        r.x = 2.0f*du - uvp[3*m2];
        r.y = 2.0f*dv - uvp[3*m2+1];
        r.z = uvp[3*m2+2];
    } else {
        int m = eidx(je, ie);
        r.x = uvp[3*m]; r.y = uvp[3*m+1]; r.z = uvp[3*m+2];
    }
    return r;
}

__global__ void __launch_bounds__(256)
build_ext_kernel(const float* __restrict__ ouv,
                 const float* __restrict__ ouv_old,
                 const float* __restrict__ ny,
                 const float* __restrict__ ebm) {
    int e = blockIdx.x * blockDim.x + threadIdx.x;
    if (e >= NEXTN) return;
    int ie = e % EX;
    int je = e / EX;

    F3 en = ext_val(ouv,     ny, je, ie);
    F3 eo = ext_val(ouv_old, ny, je, ie);
    if (e == PRESS_E) en.z = 0.0f;

    float dxx = ebm[5*e + 0];
    float dxy = ebm[5*e + 1];
    float dex = ebm[5*e + 2];
    float dey = ebm[5*e + 3];
    float Jm  = ebm[5*e + 4];
    float rJ  = 1.0f / Jm;

    g_eu [e] = en.x;  g_ev [e] = en.y;  g_ep [e] = en.z;
    g_eou[e] = eo.x;  g_eov[e] = eo.y;
    g_U  [e] = (en.x*dxx + en.y*dxy) * rJ;
    g_V  [e] = (en.x*dex + en.y*dey) * rJ;
    g_Uo [e] = (eo.x*dxx + eo.y*dxy) * rJ;
    g_Vo [e] = (eo.x*dex + eo.y*dey) * rJ;
    g_a11[e] = (dxx*dxx + dxy*dxy) * rJ;
    g_a22[e] = (dex*dex + dey*dey) * rJ;
    float pq = en.z * rJ;
    g_pxx[e] = pq * dxx;
    g_pxy[e] = pq * dxy;
    g_pex[e] = pq * dex;
    g_pey[e] = pq * dey;
}

__global__ void __launch_bounds__(256)
stencil_kernel(const float* __restrict__ ouv,
               const float* __restrict__ ouv_old,
               const float* __restrict__ obm,
               const float* __restrict__ dtg,
               const float* __restrict__ theta,
               const float* __restrict__ relp,
               float* __restrict__ out) {
    int o = blockIdx.x * blockDim.x + threadIdx.x;
    if (o >= NN) return;
    int io = o & (NXg - 1);
    int jo = o >> 10;

    int c = (jo + 1) * EX + (io + 1);
    int l = c - 1,  r = c + 1;
    int d = c - EX, u = c + EX;

    float dt    = dtg[0];
    float uc    = theta[0];
    float cc    = theta[1];
    float convc = theta[2];
    float pc    = theta[3];
    float dc    = theta[4];
    float relax = relp[0];

    // --- contravariant velocities (new) : 3-pt stencils ---
    float Uc = g_U[c], Ul = g_U[l], Ur = g_U[r];
    float Vc = g_V[c], Vd = g_V[d], Vu = g_V[u];

    float loss = 0.5f * ((Ur - Ul) + (Vu - Vd)) * cc;

    // --- velocities, ext (new) 3x3 for vis + fluxes ---
    float euc = g_eu[c], eul = g_eu[l], eur = g_eu[r], eud = g_eu[d], euu = g_eu[u];
    float evc = g_ev[c], evl = g_ev[l], evr = g_ev[r], evd = g_ev[d], evu = g_ev[u];
    float epc = g_ep[c], epl = g_ep[l], epr = g_ep[r], epd = g_ep[d], epu = g_ep[u];
    float eudl = g_eu[d-1], eudr = g_eu[d+1], euul = g_eu[u-1], euur = g_eu[u+1];
    float evdl = g_ev[d-1], evdr = g_ev[d+1], evul = g_ev[u-1], evur = g_ev[u+1];
    float epdl = g_ep[d-1], epdr = g_ep[d+1], epul = g_ep[u-1], epur = g_ep[u+1];

    // --- convection (new) ---
    float cnu = 0.25f * ((euc + eur) * (Uc + Ur) - (eul + euc) * (Ul + Uc))
              + 0.25f * ((euc + euu) * (Vc + Vu) - (eud + euc) * (Vd + Vc));
    float cnv = 0.25f * ((evc + evr) * (Uc + Ur) - (evl + evc) * (Ul + Uc))
              + 0.25f * ((evc + evu) * (Vc + Vu) - (evd + evc) * (Vd + Vc));

    // --- convection (old) ---
    float Uoc = g_Uo[c], Uol = g_Uo[l], Uor = g_Uo[r];
    float Voc = g_Vo[c], Vod = g_Vo[d], Vou = g_Vo[u];
    float ouc = g_eou[c], oul = g_eou[l], our = g_eou[r], oud = g_eou[d], ouu = g_eou[u];
    float ovc = g_eov[c], ovl = g_eov[l], ovr = g_eov[r], ovd = g_eov[d], ovu = g_eov[u];

    float cou = 0.25f * ((ouc + our) * (Uoc + Uor) - (oul + ouc) * (Uol + Uoc))
              + 0.25f * ((ouc + ouu) * (Voc + Vou) - (oud + ouc) * (Vod + Voc));
    float cov = 0.25f * ((ovc + ovr) * (Uoc + Uor) - (ovl + ovc) * (Uol + Uoc))
              + 0.25f * ((ovc + ovu) * (Voc + Vou) - (ovd + ovc) * (Vod + Voc));

    float convu = relax * cou + (1.0f - relax) * cnu;
    float convv = relax * cov + (1.0f - relax) * cnv;

    // --- diffusion (new only) ---
    float a11c = g_a11[c], a11l = g_a11[l], a11r = g_a11[r];
    float a22c = g_a22[c], a22d = g_a22[d], a22u = g_a22[u];
    float difu = 0.5f * ((a11c + a11r) * (eur - euc) - (a11l + a11c) * (euc - eul))
               + 0.5f * ((a22c + a22u) * (euu - euc) - (a22d + a22c) * (euc - eud));
    float difv = 0.5f * ((a11c + a11r) * (evr - evc) - (a11l + a11c) * (evc - evl))
               + 0.5f * ((a22c + a22u) * (evu - evc) - (a22d + a22c) * (evc - evd));

    // --- pressure gradient ---
    float gPx = 0.5f * (g_pxx[r] - g_pxx[l]) + 0.5f * (g_pex[u] - g_pex[d]);
    float gPy = 0.5f * (g_pey[u] - g_pey[d]) + 0.5f * (g_pxy[r] - g_pxy[l]);

    // --- unsteady ---
    float Jo = obm[5*o + 4];
    float inv = 1.0f / (dt * Jo);
    float unu = (ouv[3*o]   - ouv_old[3*o])   * inv;
    float unv = (ouv[3*o+1] - ouv_old[3*o+1]) * inv;

    float momu = uc * unu + convc * convu + pc * gPx - dc * difu;
    float momv = uc * unv + convc * convv + pc * gPy - dc * difv;

    // --- uvp_to_vis: (1-2-1)^2 / 16 binomial smooth of ext ---
    const float s = 1.0f / 16.0f;
    float visu = s * (4.0f*euc + 2.0f*(eul + eur + eud + euu) + (eudl + eudr + euul + euur));
    float visv = s * (4.0f*evc + 2.0f*(evl + evr + evd + evu) + (evdl + evdr + evul + evur));
    float visp = s * (4.0f*epc + 2.0f*(epl + epr + epd + epu) + (epdl + epdr + epul + epur));

    out[o]          = loss;
    out[NN + o]     = momu;
    out[2*NN + o]   = momv;
    out[3*NN + 3*o]     = visu;
    out[3*NN + 3*o + 1] = visv;
    out[3*NN + 3*o + 2] = visp;
}

extern "C" void kernel_launch(void* const* d_in, const int* in_sizes, int n_in,
                              void* d_out, int out_size) {
    const float* ouv     = (const float*)d_in[0];  // original_uv   (n,3)
    const float* ouv_old = (const float*)d_in[1];  // uv_old        (n,3)
    const float* ny      = (const float*)d_in[2];  // node_y        (n,3)
    const float* obm     = (const float*)d_in[3];  // original_block_metrics (n,5)
    const float* ebm     = (const float*)d_in[4];  // extended_block_metrics (n_ext,5)
    const float* dtg     = (const float*)d_in[5];  // dt_graph (1,1)
    const float* theta   = (const float*)d_in[6];  // pde_theta (1,5)
    const float* relp    = (const float*)d_in[7];  // relaxtion (1,1)
    float* out = (float*)d_out;

    {
        int nthreads = 256;
        int nblocks = (NEXTN + nthreads - 1) / nthreads;
        build_ext_kernel<<<nblocks, nthreads>>>(ouv, ouv_old, ny, ebm);
    }
    {
        int nthreads = 256;
        int nblocks = (NN + nthreads - 1) / nthreads;
        stencil_kernel<<<nblocks, nthreads>>>(ouv, ouv_old, obm, dtg, theta, relp, out);
    }
}

// round 2
// speedup vs baseline: 2.0202x; 2.0202x over previous
#include <cuda_runtime.h>

// FD_discretizer: fused single-kernel version.
// 1024x1024 grid, extended 1026x1026. All index arrays closed-form in (i,j).
// Key identities exploited:
//   obm = ebm[interior]  -> J_o[o] == Jm at center ext node (obm input unused)
//   interior ext == raw uvp -> unsteady from smem values directly

#define NXg 1024
#define NYg 1024
#define EX  1026
#define EY  1026
#define NN  (NXg*NYg)

#define PRESS_E (513*EX + 513)

#define TX 32
#define TY 8
#define EXT_W (TX + 2)   // 34
#define EXT_H (TY + 2)   // 10
#define TILE  (EXT_W * EXT_H)  // 340

__device__ __forceinline__ int clampi(int x, int lo, int hi) {
    return x < lo ? lo : (x > hi ? hi : x);
}
__device__ __forceinline__ int eidx(int je, int ie) {
    return clampi(je - 1, 0, NYg - 1) * NXg + clampi(ie - 1, 0, NXg - 1);
}

struct F3 { float x, y, z; };

// node_type closed-form: io==0 INFLOW, io==NX-1 OUTFLOW, j-edges WALL.
__device__ __forceinline__ void dummy_uv(const float* __restrict__ uvp,
                                         const float* __restrict__ ny,
                                         int m, float& du, float& dv) {
    int io = m % NXg;
    int jo = m / NXg;
    bool bc = (io == 0) || (io != NXg - 1 && (jo == 0 || jo == NYg - 1));
    if (bc) { du = ny[3*m]; dv = ny[3*m+1]; }
    else    { du = uvp[3*m]; dv = uvp[3*m+1]; }
}
__device__ __forceinline__ float dummy_p(const float* __restrict__ uvp, int m) {
    int io = m % NXg;
    return (io == NXg - 1) ? 0.0f : uvp[3*m+2];
}

// BC-enforced extended value at (je,ie).
__device__ __forceinline__ F3 ext_val(const float* __restrict__ uvp,
                                      const float* __restrict__ ny,
                                      int je, int ie) {
    F3 r;
    bool jin = (je >= 1) & (je <= EY - 2);
    if (ie == 0 && jin) {               // left ghost: INFLOW -> pmask
        int m1 = eidx(je, 1), m2 = eidx(je, 2);
        float du, dv; dummy_uv(uvp, ny, m1, du, dv);
        r.x = 2.0f*du - uvp[3*m2];
        r.y = 2.0f*dv - uvp[3*m2+1];
        r.z = uvp[3*m2+2];
    } else if (ie == EX - 1 && jin) {   // right ghost: OUTFLOW -> uvmask
        int m1 = eidx(je, EX - 2), m2 = eidx(je, EX - 3);
        float dp = dummy_p(uvp, m1);
        r.x = uvp[3*m2];
        r.y = uvp[3*m2+1];
        r.z = 2.0f*dp - uvp[3*m2+2];
    } else if (je == 0 && ie >= 1 && ie <= EX - 2) {   // bottom ghost: WALL
        int m1 = eidx(1, ie), m2 = eidx(2, ie);
        float du, dv; dummy_uv(uvp, ny, m1, du, dv);
        r.x = 2.0f*du - uvp[3*m2];
        r.y = 2.0f*dv - uvp[3*m2+1];
        r.z = uvp[3*m2+2];
    } else if (je == EY - 1 && ie >= 1 && ie <= EX - 2) {  // top ghost: WALL
        int m1 = eidx(EY - 2, ie), m2 = eidx(EY - 3, ie);
        float du, dv; dummy_uv(uvp, ny, m1, du, dv);
        r.x = 2.0f*du - uvp[3*m2];
        r.y = 2.0f*dv - uvp[3*m2+1];
        r.z = uvp[3*m2+2];
    } else {
        int m = eidx(je, ie);
        r.x = uvp[3*m]; r.y = uvp[3*m+1]; r.z = uvp[3*m+2];
    }
    return r;
}

__global__ void __launch_bounds__(TX*TY)
fused_kernel(const float* __restrict__ ouv,
             const float* __restrict__ ouv_old,
             const float* __restrict__ ny,
             const float* __restrict__ ebm,
             const float* __restrict__ dtg,
             const float* __restrict__ theta,
             const float* __restrict__ relp,
             float* __restrict__ out) {
    __shared__ float s_eu [TILE];
    __shared__ float s_ev [TILE];
    __shared__ float s_ep [TILE];
    __shared__ float s_eou[TILE];
    __shared__ float s_eov[TILE];
    __shared__ float s_U  [TILE];
    __shared__ float s_V  [TILE];
    __shared__ float s_Uo [TILE];
    __shared__ float s_Vo [TILE];
    __shared__ float s_a11[TILE];
    __shared__ float s_a22[TILE];
    __shared__ float s_pxx[TILE];
    __shared__ float s_pxy[TILE];
    __shared__ float s_pex[TILE];
    __shared__ float s_pey[TILE];
    __shared__ float s_Jm [TILE];

    const int bx = blockIdx.x, by = blockIdx.y;
    const int lx = threadIdx.x, ly = threadIdx.y;
    const int tid = ly * TX + lx;

    // ---- cooperative fill of extended tile ----
    #pragma unroll
    for (int s = tid; s < TILE; s += TX*TY) {
        int ly2 = s / EXT_W;
        int lx2 = s - ly2 * EXT_W;
        int ie = bx * TX + lx2;           // 0..1025
        int je = by * TY + ly2;           // 0..1025

        F3 en = ext_val(ouv,     ny, je, ie);
        F3 eo = ext_val(ouv_old, ny, je, ie);
        int e = je * EX + ie;
        if (e == PRESS_E) en.z = 0.0f;

        float dxx = ebm[5*e + 0];
        float dxy = ebm[5*e + 1];
        float dex = ebm[5*e + 2];
        float dey = ebm[5*e + 3];
        float Jm  = ebm[5*e + 4];
        float rJ  = 1.0f / Jm;

        s_eu [s] = en.x;  s_ev [s] = en.y;  s_ep [s] = en.z;
        s_eou[s] = eo.x;  s_eov[s] = eo.y;
        s_U  [s] = (en.x*dxx + en.y*dxy) * rJ;
        s_V  [s] = (en.x*dex + en.y*dey) * rJ;
        s_Uo [s] = (eo.x*dxx + eo.y*dxy) * rJ;
        s_Vo [s] = (eo.x*dex + eo.y*dey) * rJ;
        s_a11[s] = (dxx*dxx + dxy*dxy) * rJ;
        s_a22[s] = (dex*dex + dey*dey) * rJ;
        float pq = en.z * rJ;
        s_pxx[s] = pq * dxx;
        s_pxy[s] = pq * dxy;
        s_pex[s] = pq * dex;
        s_pey[s] = pq * dey;
        s_Jm [s] = Jm;
    }
    __syncthreads();

    // ---- per-output stencils from smem ----
    const int io = bx * TX + lx;
    const int jo = by * TY + ly;
    const int o  = jo * NXg + io;

    const int c = (ly + 1) * EXT_W + (lx + 1);
    const int l = c - 1,      r = c + 1;
    const int d = c - EXT_W,  u = c + EXT_W;

    const float dt    = __ldg(dtg);
    const float uc    = __ldg(theta + 0);
    const float cc    = __ldg(theta + 1);
    const float convc = __ldg(theta + 2);
    const float pc    = __ldg(theta + 3);
    const float dc    = __ldg(theta + 4);
    const float relax = __ldg(relp);

    float Uc = s_U[c], Ul = s_U[l], Ur = s_U[r];
    float Vc = s_V[c], Vd = s_V[d], Vu = s_V[u];
    float loss = 0.5f * ((Ur - Ul) + (Vu - Vd)) * cc;

    float euc = s_eu[c], eul = s_eu[l], eur = s_eu[r], eud = s_eu[d], euu = s_eu[u];
    float evc = s_ev[c], evl = s_ev[l], evr = s_ev[r], evd = s_ev[d], evu = s_ev[u];
    float epc = s_ep[c], epl = s_ep[l], epr = s_ep[r], epd = s_ep[d], epu = s_ep[u];
    float eudl = s_eu[d-1], eudr = s_eu[d+1], euul = s_eu[u-1], euur = s_eu[u+1];
    float evdl = s_ev[d-1], evdr = s_ev[d+1], evul = s_ev[u-1], evur = s_ev[u+1];
    float epdl = s_ep[d-1], epdr = s_ep[d+1], epul = s_ep[u-1], epur = s_ep[u+1];

    // convection (new)
    float cnu = 0.25f * ((euc + eur) * (Uc + Ur) - (eul + euc) * (Ul + Uc))
              + 0.25f * ((euc + euu) * (Vc + Vu) - (eud + euc) * (Vd + Vc));
    float cnv = 0.25f * ((evc + evr) * (Uc + Ur) - (evl + evc) * (Ul + Uc))
              + 0.25f * ((evc + evu) * (Vc + Vu) - (evd + evc) * (Vd + Vc));

    // convection (old)
    float Uoc = s_Uo[c], Uol = s_Uo[l], Uor = s_Uo[r];
    float Voc = s_Vo[c], Vod = s_Vo[d], Vou = s_Vo[u];
    float ouc = s_eou[c], oul = s_eou[l], our = s_eou[r], oud = s_eou[d], ouu = s_eou[u];
    float ovc = s_eov[c], ovl = s_eov[l], ovr = s_eov[r], ovd = s_eov[d], ovu = s_eov[u];

    float cou = 0.25f * ((ouc + our) * (Uoc + Uor) - (oul + ouc) * (Uol + Uoc))
              + 0.25f * ((ouc + ouu) * (Voc + Vou) - (oud + ouc) * (Vod + Voc));
    float cov = 0.25f * ((ovc + ovr) * (Uoc + Uor) - (ovl + ovc) * (Uol + Uoc))
              + 0.25f * ((ovc + ovu) * (Voc + Vou) - (ovd + ovc) * (Vod + Voc));

    float convu = relax * cou + (1.0f - relax) * cnu;
    float convv = relax * cov + (1.0f - relax) * cnv;

    // diffusion (new)
    float a11c = s_a11[c], a11l = s_a11[l], a11r = s_a11[r];
    float a22c = s_a22[c], a22d = s_a22[d], a22u = s_a22[u];
    float difu = 0.5f * ((a11c + a11r) * (eur - euc) - (a11l + a11c) * (euc - eul))
               + 0.5f * ((a22c + a22u) * (euu - euc) - (a22d + a22c) * (euc - eud));
    float difv = 0.5f * ((a11c + a11r) * (evr - evc) - (a11l + a11c) * (evc - evl))
               + 0.5f * ((a22c + a22u) * (evu - evc) - (a22d + a22c) * (evc - evd));

    // pressure gradient
    float gPx = 0.5f * (s_pxx[r] - s_pxx[l]) + 0.5f * (s_pex[u] - s_pex[d]);
    float gPy = 0.5f * (s_pey[u] - s_pey[d]) + 0.5f * (s_pxy[r] - s_pxy[l]);

    // unsteady: original_uv - uv_old at interior == s_eu/s_eou values; J_o == Jm[c]
    float inv = 1.0f / (dt * s_Jm[c]);
    float unu = (euc - ouc) * inv;
    float unv = (evc - ovc) * inv;

    float momu = uc * unu + convc * convu + pc * gPx - dc * difu;
    float momv = uc * unv + convc * convv + pc * gPy - dc * difv;

    // uvp_to_vis: (1-2-1)^2 / 16 binomial
    const float sw = 1.0f / 16.0f;
    float visu = sw * (4.0f*euc + 2.0f*(eul + eur + eud + euu) + (eudl + eudr + euul + euur));
    float visv = sw * (4.0f*evc + 2.0f*(evl + evr + evd + evu) + (evdl + evdr + evul + evur));
    float visp = sw * (4.0f*epc + 2.0f*(epl + epr + epd + epu) + (epdl + epdr + epul + epur));

    out[o]          = loss;
    out[NN + o]     = momu;
    out[2*NN + o]   = momv;
    out[3*NN + 3*o]     = visu;
    out[3*NN + 3*o + 1] = visv;
    out[3*NN + 3*o + 2] = visp;
}

extern "C" void kernel_launch(void* const* d_in, const int* in_sizes, int n_in,
                              void* d_out, int out_size) {
    const float* ouv     = (const float*)d_in[0];
    const float* ouv_old = (const float*)d_in[1];
    const float* ny      = (const float*)d_in[2];
    // d_in[3] (obm) unused: obm == ebm[interior]
    const float* ebm     = (const float*)d_in[4];
    const float* dtg     = (const float*)d_in[5];
    const float* theta   = (const float*)d_in[6];
    const float* relp    = (const float*)d_in[7];
    float* out = (float*)d_out;

    dim3 block(TX, TY);
    dim3 grid(NXg / TX, NYg / TY);
    fused_kernel<<<grid, block>>>(ouv, ouv_old, ny, ebm, dtg, theta, relp, out);
}